// round 10
// baseline (speedup 1.0000x reference)
#include <cuda_runtime.h>
#include <math.h>

// ---- problem constants -----------------------------------------------------
constexpr int NN   = 62;    // nodes per graph
constexpr int NP   = 64;    // padded nodes
constexpr int BB   = 512;   // graphs
constexpr int FIN  = 128;   // input features
constexpr int HH   = 64;    // hidden
constexpr int CC   = 3;     // classes

// smem regions (floats); strides are power-of-2, banks fixed by quad swizzle
constexpr int SZ_X    = NP * FIN;     // 8192
constexpr int SZ_W1   = HH * FIN;     // 8192
constexpr int SZ_A2   = NP * NP;      // 4096
constexpr int SZ_MT   = HH * NP;      // 4096  (M transposed: [h][node])
constexpr int SZ_B1   = HH;           // 64
constexpr int SZ_POOL = 16 * HH;      // 1024
constexpr int SZ_PD   = HH;           // 64
constexpr int SMEM_FLOATS = SZ_X + SZ_W1 + SZ_A2 + SZ_MT + SZ_B1 + SZ_POOL + SZ_PD;

__device__ float g_A2S[NP * NP];    // A^2, rows quad-swizzled
__device__ float g_W1S[HH * FIN];   // W1 [h][k], rows quad-swizzled

// 16B-quad swizzle within 128B groups: key = (row>>2)&7
__host__ __device__ __forceinline__ int swz(int q, int key) {
    return (q & ~7) | ((q & 7) ^ key);
}

__device__ __forceinline__ void fma2(unsigned long long& d,
                                     unsigned long long a,
                                     unsigned long long b) {
    asm("fma.rn.f32x2 %0, %1, %2, %0;" : "+l"(d) : "l"(a), "l"(b));
}
__device__ __forceinline__ float pairsum(unsigned long long v) {
    float lo, hi;
    asm("mov.b64 {%0,%1}, %2;" : "=f"(lo), "=f"(hi) : "l"(v));
    return lo + hi;
}

// ---- prep: 64 blocks x 64 threads. Block b -> A2 row b (swizzled) and
// swizzles W1 row b. A2 = D (A D^2 A) D, A never normalized in place. -------
__global__ void prep_kernel(const float* __restrict__ tril,
                            const float* __restrict__ W1) {
    __shared__ float A[NP][NP];
    __shared__ float dv[NP];
    __shared__ float d2[NP];
    __shared__ float trow[NP];
    const int j = threadIdx.x;    // 0..63
    const int b = blockIdx.x;     // 0..63

    for (int idx = j; idx < NP * NP; idx += 64) {
        int i = idx >> 6, jj = idx & 63;
        float v = 0.f;
        if (i < NN && jj < NN) {
            int a_ = i > jj ? i : jj;
            int b_ = i > jj ? jj : i;
            v = tril[a_ * (a_ + 1) / 2 + b_];
        }
        A[i][jj] = v;
    }
    __syncthreads();

    {
        float s = 0.f;
        #pragma unroll 4
        for (int k = 0; k < NP; ++k) s += fabsf(A[j][k]);
        float di = s > 0.f ? rsqrtf(s) : 0.f;
        dv[j] = di;
        d2[j] = di * di;
    }
    __syncthreads();

    trow[j] = A[b][j] * d2[j];
    __syncthreads();

    {
        float s = 0.f;
        #pragma unroll 4
        for (int k = 0; k < NP; ++k) s += trow[k] * A[k][j];
        // swizzled store: row b, element j
        int q = j >> 2;
        int pos = swz(q, (b >> 2) & 7) * 4 + (j & 3);
        g_A2S[b * NP + pos] = dv[b] * s * dv[j];
    }

    // swizzle W1 row b: g_W1S[b][swz] = W1[b][k]
    for (int k = j; k < FIN; k += 64) {
        int q = k >> 2;
        int pos = swz(q, (b >> 2) & 7) * 4 + (k & 3);
        g_W1S[b * FIN + pos] = W1[b * FIN + k];
    }
}

// ---- main: 512 CTAs x 256 threads; k-paired FFMA2, swizzled smem -----------
__global__ __launch_bounds__(256, 2)
void graph_kernel(const float* __restrict__ x,
                  const float* __restrict__ b1,
                  const float* __restrict__ W2,
                  const float* __restrict__ b2,
                  float* __restrict__ out) {
    extern __shared__ float sm[];
    float* sX      = sm;                      // [64][128] swizzled rows
    float* sW1     = sX   + SZ_X;             // [64][128] swizzled rows
    float* sA2     = sW1  + SZ_W1;            // [64][64]  swizzled rows
    float* sMT     = sA2  + SZ_A2;            // [64][64]  swizzled rows (M^T)
    float* sB1     = sMT  + SZ_MT;            // 64
    float* sPool   = sB1  + SZ_B1;            // [16][64]
    float* sPooled = sPool + SZ_POOL;         // 64

    const int tid   = threadIdx.x;
    const int g     = blockIdx.x;
    const int lane  = tid & 31;
    const int w     = tid >> 5;
    const int rtile = (w & 1) * 8 + (lane >> 2);   // 0..15
    const int ctile = (w >> 1) * 4 + (lane & 3);   // 0..15
    const int r0    = rtile * 4;
    const int c0    = ctile * 4;
    const int keyR  = rtile & 7;
    const int keyC  = ctile & 7;

    // ---- stage 0: stage X (swizzled, zero-padded), W1S/A2S (plain copy) ----
    const float4* xg = (const float4*)(x + (size_t)g * NN * FIN);
    for (int t = tid; t < NP * 32; t += 256) {
        int i = t >> 5, q = t & 31;
        float4 v = (i < NN) ? xg[i * 32 + q]
                            : make_float4(0.f, 0.f, 0.f, 0.f);
        *(float4*)(sX + i * FIN + swz(q, (i >> 2) & 7) * 4) = v;
    }
    const float4* w1s4 = (const float4*)g_W1S;
    for (int t = tid; t < SZ_W1 / 4; t += 256) ((float4*)sW1)[t] = w1s4[t];
    const float4* a2s4 = (const float4*)g_A2S;
    for (int t = tid; t < SZ_A2 / 4; t += 256) ((float4*)sA2)[t] = a2s4[t];
    if (tid < HH) sB1[tid] = b1[tid];
    __syncthreads();

    // ---- stage 1: M = X @ W1^T, k-paired FFMA2; write M^T (swizzled) ----
    {
        unsigned long long acc[16];
        #pragma unroll
        for (int i = 0; i < 16; ++i) acc[i] = 0ull;

        #pragma unroll 2
        for (int q = 0; q < 32; ++q) {               // quad = 4 k values = 2 pairs
            const int pr = swz(q, keyR) * 4;
            const int pc = swz(q, keyC) * 4;
            ulonglong2 xv[4], wv[4];
            #pragma unroll
            for (int r = 0; r < 4; ++r)
                xv[r] = *(const ulonglong2*)(sX + (r0 + r) * FIN + pr);
            #pragma unroll
            for (int c = 0; c < 4; ++c)
                wv[c] = *(const ulonglong2*)(sW1 + (c0 + c) * FIN + pc);
            #pragma unroll
            for (int r = 0; r < 4; ++r)
                #pragma unroll
                for (int c = 0; c < 4; ++c) {
                    fma2(acc[r * 4 + c], xv[r].x, wv[c].x);
                    fma2(acc[r * 4 + c], xv[r].y, wv[c].y);
                }
        }
        // reduce pairs, store M^T: row (c0+c) holds node dimension
        const int pm = swz(rtile, keyC) * 4;         // quad rtile in MT row
        #pragma unroll
        for (int c = 0; c < 4; ++c) {
            float m0 = pairsum(acc[0 * 4 + c]);
            float m1 = pairsum(acc[1 * 4 + c]);
            float m2 = pairsum(acc[2 * 4 + c]);
            float m3 = pairsum(acc[3 * 4 + c]);
            *(float4*)(sMT + (c0 + c) * NP + pm) = make_float4(m0, m1, m2, m3);
        }
    }
    __syncthreads();

    // ---- stage 2: Y = A2 @ M (via A2 rows x M^T rows), relu+b1, pool ----
    {
        unsigned long long acc[16];
        #pragma unroll
        for (int i = 0; i < 16; ++i) acc[i] = 0ull;

        #pragma unroll 2
        for (int q = 0; q < 16; ++q) {
            const int pr = swz(q, keyR) * 4;
            const int pc = swz(q, keyC) * 4;
            ulonglong2 av[4], mv[4];
            #pragma unroll
            for (int r = 0; r < 4; ++r)
                av[r] = *(const ulonglong2*)(sA2 + (r0 + r) * NP + pr);
            #pragma unroll
            for (int c = 0; c < 4; ++c)
                mv[c] = *(const ulonglong2*)(sMT + (c0 + c) * NP + pc);
            #pragma unroll
            for (int r = 0; r < 4; ++r)
                #pragma unroll
                for (int c = 0; c < 4; ++c) {
                    fma2(acc[r * 4 + c], av[r].x, mv[c].x);
                    fma2(acc[r * 4 + c], av[r].y, mv[c].y);
                }
        }

        float4 bb = *(const float4*)(sB1 + c0);
        float part[4] = {0.f, 0.f, 0.f, 0.f};
        #pragma unroll
        for (int r = 0; r < 4; ++r) {
            if (r0 + r < NN) {   // padding rows: Y=0 but relu(b1)!=0 -> mask
                part[0] += fmaxf(pairsum(acc[r * 4 + 0]) + bb.x, 0.f);
                part[1] += fmaxf(pairsum(acc[r * 4 + 1]) + bb.y, 0.f);
                part[2] += fmaxf(pairsum(acc[r * 4 + 2]) + bb.z, 0.f);
                part[3] += fmaxf(pairsum(acc[r * 4 + 3]) + bb.w, 0.f);
            }
        }
        *(float4*)(sPool + rtile * HH + c0) =
            make_float4(part[0], part[1], part[2], part[3]);
    }
    __syncthreads();

    // ---- stage 3: reduce pool -> latent; tiny head + log_softmax ----
    if (tid < HH) {
        float p = 0.f;
        #pragma unroll
        for (int t = 0; t < 16; ++t) p += sPool[t * HH + tid];
        sPooled[tid] = p;
        out[(size_t)g * HH + tid] = p;          // latent_v
    }
    __syncthreads();

    if (tid < 32) {
        float p0 = sPooled[tid], p1 = sPooled[tid + 32];
        float l[CC];
        #pragma unroll
        for (int cc = 0; cc < CC; ++cc) {
            l[cc] = p0 * W2[cc * HH + tid] + p1 * W2[cc * HH + tid + 32];
            #pragma unroll
            for (int off = 16; off; off >>= 1)
                l[cc] += __shfl_xor_sync(0xffffffffu, l[cc], off);
        }
        if (tid == 0) {
            float l0 = l[0] + b2[0];
            float l1 = l[1] + b2[1];
            float l2 = l[2] + b2[2];
            float m  = fmaxf(l0, fmaxf(l1, l2));
            float lse = m + logf(expf(l0 - m) + expf(l1 - m) + expf(l2 - m));
            float* lp = out + (size_t)BB * HH + (size_t)g * CC;
            lp[0] = l0 - lse;
            lp[1] = l1 - lse;
            lp[2] = l2 - lse;
        }
    }
}

// ---- launch -----------------------------------------------------------------
extern "C" void kernel_launch(void* const* d_in, const int* in_sizes, int n_in,
                              void* d_out, int out_size) {
    (void)in_sizes; (void)n_in; (void)out_size;
    const float* x    = (const float*)d_in[0];
    const float* tril = (const float*)d_in[1];
    const float* W1   = (const float*)d_in[2];
    const float* b1   = (const float*)d_in[3];
    const float* W2   = (const float*)d_in[4];
    const float* b2   = (const float*)d_in[5];
    float* out = (float*)d_out;

    const int smem_bytes = SMEM_FLOATS * (int)sizeof(float);
    cudaFuncSetAttribute(graph_kernel,
                         cudaFuncAttributeMaxDynamicSharedMemorySize, smem_bytes);

    prep_kernel<<<64, 64>>>(tril, W1);
    graph_kernel<<<BB, 256, smem_bytes>>>(x, b1, W2, b2, out);
}